// round 5
// baseline (speedup 1.0000x reference)
#include <cuda_runtime.h>
#include <cuda_fp16.h>
#include <cstdint>

#define DD 256
#define BB 16
#define NN 2048
#define ROWS (BB*NN)

typedef __half h16;

// ------------------------------------------------------------------ scratch
__device__ float g_W[DD*DD];                 // Wq @ Wk^T
__device__ float g_u[DD];                    // Wk @ bq
__device__ float g_c[ROWS];                  // X . u  (per key row)
__device__ float g_invl[ROWS];               // 1 / sum(Ph)
__device__ float g_S[(size_t)ROWS*NN];       // scores (268MB)

__device__ h16 g_Xh[(size_t)ROWS*DD],  g_Xl[(size_t)ROWS*DD];    // X splits (row-major)
__device__ h16 g_Xth[(size_t)BB*DD*NN], g_Xtl[(size_t)BB*DD*NN]; // X^T splits
__device__ h16 g_Aph[(size_t)ROWS*DD], g_Apl[(size_t)ROWS*DD];   // A' = X@W splits
__device__ h16 g_Ph[(size_t)ROWS*NN];                            // softmax (hi only)
__device__ h16 g_aggh[(size_t)ROWS*DD], g_aggl[(size_t)ROWS*DD]; // agg splits
__device__ h16 g_Wth[DD*DD], g_Wtl[DD*DD];   // (WqWk^T)^T splits
__device__ h16 g_Woth[DD*DD], g_Wotl[DD*DD]; // Wo^T splits

// ------------------------------------------------------------------ helpers
__device__ __forceinline__ uint32_t smem_u32(const void* p) {
    uint32_t a;
    asm("{ .reg .u64 t; cvta.to.shared.u64 t, %1; cvt.u32.u64 %0, t; }" : "=r"(a) : "l"(p));
    return a;
}
#define CP16(dst, src) \
    asm volatile("cp.async.cg.shared.global [%0], [%1], 16;" :: "r"(dst), "l"(src))
#define CP_COMMIT() asm volatile("cp.async.commit_group;" ::: "memory")
#define CP_WAIT(n)  asm volatile("cp.async.wait_group %0;" :: "n"(n) : "memory")

#define MMA16816(c, a, b)                                                     \
    asm volatile("mma.sync.aligned.m16n8k16.row.col.f32.f16.f16.f32 "         \
        "{%0,%1,%2,%3},{%4,%5,%6,%7},{%8,%9},{%0,%1,%2,%3};"                  \
        : "+f"((c)[0]), "+f"((c)[1]), "+f"((c)[2]), "+f"((c)[3])              \
        : "r"((a)[0]), "r"((a)[1]), "r"((a)[2]), "r"((a)[3]),                 \
          "r"((b)[0]), "r"((b)[1]))

#define LDSM4(r0, r1, r2, r3, addr)                                           \
    asm volatile("ldmatrix.sync.aligned.m8n8.x4.shared.b16 {%0,%1,%2,%3}, [%4];" \
        : "=r"(r0), "=r"(r1), "=r"(r2), "=r"(r3) : "r"(addr))

__device__ __forceinline__ void split2(float f, h16& h, h16& l) {
    h = __float2half_rn(f);
    l = __float2half_rn(f - __half2float(h));
}

// ------------------------------------------------------------------ precompute: W = Wq@Wk^T, u = Wk@bq
__global__ void k_precomp(const float* __restrict__ Wq, const float* __restrict__ Wk,
                          const float* __restrict__ bq) {
    __shared__ float v[DD];
    int bx = blockIdx.x;
    if (bx < DD) {
        v[threadIdx.x] = Wq[bx*DD + threadIdx.x];
        __syncthreads();
        int j = threadIdx.x;
        const float* wk = Wk + j*DD;
        float s = 0.f;
#pragma unroll 8
        for (int e = 0; e < DD; e++) s += v[e] * wk[e];
        g_W[bx*DD + j] = s;
    } else {
        v[threadIdx.x] = bq[threadIdx.x];
        __syncthreads();
        int i = threadIdx.x;
        const float* wk = Wk + i*DD;
        float s = 0.f;
#pragma unroll 8
        for (int e = 0; e < DD; e++) s += wk[e] * v[e];
        g_u[i] = s;
    }
}

// ------------------------------------------------------------------ fused prep
__global__ __launch_bounds__(256) void k_prep(const float* __restrict__ X,
                                              const float* __restrict__ Wo) {
    __shared__ float t[64][65];
    __shared__ float us[DD];
    int bx = blockIdx.x, tid = threadIdx.x;
    if (bx < 512) {
        int which = bx >> 8, j = bx & 255, d = tid;
        const float* src = which ? Wo : g_W;
        h16* dh = which ? g_Woth : g_Wth;
        h16* dl = which ? g_Wotl : g_Wtl;
        float f = src[d*DD + j];
        split2(f, dh[j*DD + d], dl[j*DD + d]);
    } else if (bx < 4608) {
        if (tid < DD) us[tid] = g_u[tid];
        __syncthreads();
        int warp = (bx - 512)*8 + (tid >> 5);
        int lane = tid & 31;
        const float* x = X + (size_t)warp * DD;
        float c = 0.f;
#pragma unroll
        for (int i = 0; i < 8; i++) {
            int e = lane + 32*i;
            float f = x[e];
            c += f * us[e];
            split2(f, g_Xh[(size_t)warp*DD + e], g_Xl[(size_t)warp*DD + e]);
        }
#pragma unroll
        for (int o = 16; o; o >>= 1) c += __shfl_xor_sync(0xffffffffu, c, o);
        if (lane == 0) g_c[warp] = c;
    } else {
        int idx = bx - 4608;
        int n0 = (idx & 31) * 64, d0 = ((idx >> 5) & 3) * 64, b = idx >> 7;
        const float* Xb = X + (size_t)b * NN * DD;
        for (int u = tid; u < 64*16; u += 256) {
            int r = u >> 4, c4 = u & 15;
            float4 v = *(const float4*)(Xb + (size_t)(n0 + r)*DD + d0 + c4*4);
            t[r][c4*4+0] = v.x; t[r][c4*4+1] = v.y; t[r][c4*4+2] = v.z; t[r][c4*4+3] = v.w;
        }
        __syncthreads();
        size_t ob = (size_t)b * DD * NN;
        for (int u = tid; u < 4096; u += 256) {
            int r = u >> 6, c = u & 63;
            split2(t[c][r], g_Xth[ob + (size_t)(d0 + r)*NN + n0 + c],
                            g_Xtl[ob + (size_t)(d0 + r)*NN + n0 + c]);
        }
    }
}

// warp per row softmax (vectorized): Ph = fp16(exp(S + c - max)), invl = 1/sum(Ph)
__global__ __launch_bounds__(256) void k_softmax() {
    int warp = (blockIdx.x * blockDim.x + threadIdx.x) >> 5;
    int lane = threadIdx.x & 31;
    int b = warp >> 11;
    const float* srow = g_S + (size_t)warp * NN;
    const float* crow = g_c + (size_t)b * NN;
    float4 v4[16];
    float mx = -1e30f;
#pragma unroll
    for (int i = 0; i < 16; i++) {
        float4 s = *(const float4*)(srow + i*128 + lane*4);
        float4 cc = *(const float4*)(crow + i*128 + lane*4);
        s.x += cc.x; s.y += cc.y; s.z += cc.z; s.w += cc.w;
        v4[i] = s;
        mx = fmaxf(mx, fmaxf(fmaxf(s.x, s.y), fmaxf(s.z, s.w)));
    }
#pragma unroll
    for (int o = 16; o; o >>= 1) mx = fmaxf(mx, __shfl_xor_sync(0xffffffffu, mx, o));
    float sum = 0.f;
    size_t ro = (size_t)warp * NN;
#pragma unroll
    for (int i = 0; i < 16; i++) {
        float e0 = __expf(v4[i].x - mx), e1 = __expf(v4[i].y - mx);
        float e2 = __expf(v4[i].z - mx), e3 = __expf(v4[i].w - mx);
        h16 h0 = __float2half_rn(e0), h1 = __float2half_rn(e1);
        h16 h2 = __float2half_rn(e2), h3 = __float2half_rn(e3);
        sum += __half2float(h0) + __half2float(h1) + __half2float(h2) + __half2float(h3);
        __half2 p01 = __halves2half2(h0, h1), p23 = __halves2half2(h2, h3);
        uint2 pk;
        pk.x = *reinterpret_cast<uint32_t*>(&p01);
        pk.y = *reinterpret_cast<uint32_t*>(&p23);
        *(uint2*)(g_Ph + ro + i*128 + lane*4) = pk;
    }
#pragma unroll
    for (int o = 16; o; o >>= 1) sum += __shfl_xor_sync(0xffffffffu, sum, o);
    if (lane == 0) g_invl[warp] = 1.f / sum;
}

// ------------------------------------------------------------------ HMMA GEMM
// C tile 128x128 = sum_k combos of fp16 splits. SKIP_AL: A hi only (2 combos).
// 3-stage cp.async pipeline, ldmatrix fragment loads, 1 barrier per 32-K chunk.
#define TPAD   40                 // 32 data + 8 pad halfs per row -> 80B
#define TILE_B (128*TPAD*2)       // 10240
#define OFF_AH 0
#define OFF_AL (1*TILE_B)
#define OFF_BH (2*TILE_B)
#define OFF_BL (3*TILE_B)
#define STAGE_B (4*TILE_B)        // 40960
#define NSTAGE 3
#define GEMM_SMEM (NSTAGE*STAGE_B)  // 122880

template<bool SKIP_AL>
__device__ __forceinline__ void issue_chunk(
    uint32_t sbase, const h16* __restrict__ pAh, const h16* __restrict__ pAl,
    const h16* __restrict__ pBh, const h16* __restrict__ pBl,
    int K, int k0, int tid)
{
#pragma unroll
    for (int i = 0; i < 2; i++) {
        int idx = tid + 256*i;
        int row = idx >> 2, seg = idx & 3;
        uint32_t doff = (uint32_t)(row*80 + seg*16);
        size_t goff = (size_t)row*K + k0 + seg*8;
        CP16(sbase + OFF_AH + doff, pAh + goff);
        if (!SKIP_AL) CP16(sbase + OFF_AL + doff, pAl + goff);
        CP16(sbase + OFF_BH + doff, pBh + goff);
        CP16(sbase + OFF_BL + doff, pBl + goff);
    }
}

// EPI: 0 = fp32   1 = fp16 hi/lo split with optional 1/l row scale   2 = bias+relu fp32
template<int EPI, bool SKIP_AL>
__global__ __launch_bounds__(256) void k_gemm(
    const h16* __restrict__ Ah, const h16* __restrict__ Al,
    const h16* __restrict__ Bh, const h16* __restrict__ Bl,
    float* __restrict__ Cf, h16* __restrict__ Ch, h16* __restrict__ Cl,
    const float* __restrict__ bias, const float* __restrict__ invl,
    int K, int ldc, int Mrows, size_t sA, size_t sB, size_t sC)
{
    extern __shared__ char smem[];
    uint32_t sb = smem_u32(smem);
    int tid = threadIdx.x;
    int lane = tid & 31, wid = tid >> 5;
    int g = lane >> 2, t = lane & 3;
    int warp_m = (wid & 1) * 64;
    int warp_n = (wid >> 1) * 32;
    int m0 = blockIdx.x * 128, n0 = blockIdx.y * 128, b = blockIdx.z;

    // per-lane ldmatrix byte offsets within a tile (x4: 4 8x8 pieces)
    int lr = ((lane >> 3) & 1) * 8 + (lane & 7);
    int lk = (lane >> 4) * 16;
    uint32_t a_off[4], b_off[2];
#pragma unroll
    for (int i = 0; i < 4; i++) a_off[i] = (uint32_t)((warp_m + i*16 + lr)*80 + lk);
#pragma unroll
    for (int p = 0; p < 2; p++) b_off[p] = (uint32_t)((warp_n + p*16 + lr)*80 + lk);

    const h16* pAh = Ah + (size_t)b*sA + (size_t)m0*K;
    const h16* pAl = SKIP_AL ? nullptr : Al + (size_t)b*sA + (size_t)m0*K;
    const h16* pBh = Bh + (size_t)b*sB + (size_t)n0*K;
    const h16* pBl = Bl + (size_t)b*sB + (size_t)n0*K;

    float acc[4][4][4];
#pragma unroll
    for (int i = 0; i < 4; i++)
#pragma unroll
        for (int j = 0; j < 4; j++)
#pragma unroll
            for (int r = 0; r < 4; r++) acc[i][j][r] = 0.f;

    int nchunk = K >> 5;
    issue_chunk<SKIP_AL>(sb, pAh, pAl, pBh, pBl, K, 0, tid);
    CP_COMMIT();
    issue_chunk<SKIP_AL>(sb + STAGE_B, pAh, pAl, pBh, pBl, K, 32, tid);
    CP_COMMIT();

    int st = 0, st2 = 2;
    for (int ch = 0; ch < nchunk; ch++) {
        CP_WAIT(1);
        __syncthreads();

        uint32_t base = sb + (uint32_t)st * STAGE_B;
#pragma unroll
        for (int ks = 0; ks < 2; ks++) {
            uint32_t kb = ks * 32;
            uint32_t ah[4][4], al[4][4], bh[4][2], bl[4][2];
#pragma unroll
            for (int i = 0; i < 4; i++) {
                LDSM4(ah[i][0], ah[i][1], ah[i][2], ah[i][3], base + OFF_AH + a_off[i] + kb);
                if (!SKIP_AL)
                    LDSM4(al[i][0], al[i][1], al[i][2], al[i][3], base + OFF_AL + a_off[i] + kb);
            }
#pragma unroll
            for (int p = 0; p < 2; p++) {
                LDSM4(bh[2*p][0], bh[2*p+1][0], bh[2*p][1], bh[2*p+1][1],
                      base + OFF_BH + b_off[p] + kb);
                LDSM4(bl[2*p][0], bl[2*p+1][0], bl[2*p][1], bl[2*p+1][1],
                      base + OFF_BL + b_off[p] + kb);
            }
#pragma unroll
            for (int i = 0; i < 4; i++)
#pragma unroll
                for (int j = 0; j < 4; j++) {
                    MMA16816(acc[i][j], ah[i], bh[j]);
                    MMA16816(acc[i][j], ah[i], bl[j]);
                    if (!SKIP_AL) MMA16816(acc[i][j], al[i], bh[j]);
                }
        }

        if (ch + 2 < nchunk)
            issue_chunk<SKIP_AL>(sb + (uint32_t)st2 * STAGE_B, pAh, pAl, pBh, pBl,
                                 K, (ch+2) << 5, tid);
        CP_COMMIT();
        st = (st == NSTAGE-1) ? 0 : st + 1;
        st2 = (st2 == NSTAGE-1) ? 0 : st2 + 1;
    }

    // ---- epilogue ----
#pragma unroll
    for (int i = 0; i < 4; i++) {
        int row0 = m0 + warp_m + i*16 + g;
        float sc0 = 1.f, sc1 = 1.f;
        if (EPI == 1 && invl) {
            sc0 = invl[(size_t)b*Mrows + row0];
            sc1 = invl[(size_t)b*Mrows + row0 + 8];
        }
#pragma unroll
        for (int j = 0; j < 4; j++) {
            int col = n0 + warp_n + j*8 + 2*t;
            if (EPI == 0) {
                float* d0 = Cf + (size_t)b*sC + (size_t)row0*ldc + col;
                float* d1 = d0 + 8*ldc;
                *(float2*)d0 = make_float2(acc[i][j][0], acc[i][j][1]);
                *(float2*)d1 = make_float2(acc[i][j][2], acc[i][j][3]);
            } else if (EPI == 1) {
                float v0 = acc[i][j][0]*sc0, v1 = acc[i][j][1]*sc0;
                float v2 = acc[i][j][2]*sc1, v3 = acc[i][j][3]*sc1;
                h16 h0, l0, h1, l1, h2, l2, h3, l3;
                split2(v0, h0, l0); split2(v1, h1, l1);
                split2(v2, h2, l2); split2(v3, h3, l3);
                size_t o0 = (size_t)b*sC + (size_t)row0*ldc + col;
                size_t o1 = o0 + 8*(size_t)ldc;
                *(__half2*)(Ch + o0) = __halves2half2(h0, h1);
                *(__half2*)(Ch + o1) = __halves2half2(h2, h3);
                *(__half2*)(Cl + o0) = __halves2half2(l0, l1);
                *(__half2*)(Cl + o1) = __halves2half2(l2, l3);
            } else {
                float b0 = bias[col], b1 = bias[col+1];
                float* d0 = Cf + (size_t)row0*ldc + col;
                float* d1 = d0 + 8*ldc;
                *(float2*)d0 = make_float2(fmaxf(acc[i][j][0]+b0, 0.f),
                                           fmaxf(acc[i][j][1]+b1, 0.f));
                *(float2*)d1 = make_float2(fmaxf(acc[i][j][2]+b0, 0.f),
                                           fmaxf(acc[i][j][3]+b1, 0.f));
            }
        }
    }
}

// ------------------------------------------------------------------ launch
extern "C" void kernel_launch(void* const* d_in, const int* in_sizes, int n_in,
                              void* d_out, int out_size) {
    const float* inp = (const float*)d_in[0];
    const float* Wq  = (const float*)d_in[1];
    const float* bq  = (const float*)d_in[2];
    const float* Wk  = (const float*)d_in[3];
    // bk (d_in[4]) provably drops out of the softmax — unused.
    const float* Wo  = (const float*)d_in[5];
    const float* bo  = (const float*)d_in[6];
    float* out = (float*)d_out;

    float *pS, *pInvl;
    h16 *pXh, *pXl, *pXth, *pXtl, *pAph, *pApl, *pPh, *pAggh, *pAggl;
    h16 *pWth, *pWtl, *pWoth, *pWotl;
    cudaGetSymbolAddress((void**)&pS, g_S);
    cudaGetSymbolAddress((void**)&pInvl, g_invl);
    cudaGetSymbolAddress((void**)&pXh, g_Xh);   cudaGetSymbolAddress((void**)&pXl, g_Xl);
    cudaGetSymbolAddress((void**)&pXth, g_Xth); cudaGetSymbolAddress((void**)&pXtl, g_Xtl);
    cudaGetSymbolAddress((void**)&pAph, g_Aph); cudaGetSymbolAddress((void**)&pApl, g_Apl);
    cudaGetSymbolAddress((void**)&pPh, g_Ph);
    cudaGetSymbolAddress((void**)&pAggh, g_aggh); cudaGetSymbolAddress((void**)&pAggl, g_aggl);
    cudaGetSymbolAddress((void**)&pWth, g_Wth); cudaGetSymbolAddress((void**)&pWtl, g_Wtl);
    cudaGetSymbolAddress((void**)&pWoth, g_Woth); cudaGetSymbolAddress((void**)&pWotl, g_Wotl);

    cudaFuncSetAttribute((const void*)k_gemm<0,false>, cudaFuncAttributeMaxDynamicSharedMemorySize, GEMM_SMEM);
    cudaFuncSetAttribute((const void*)k_gemm<1,false>, cudaFuncAttributeMaxDynamicSharedMemorySize, GEMM_SMEM);
    cudaFuncSetAttribute((const void*)k_gemm<1,true>,  cudaFuncAttributeMaxDynamicSharedMemorySize, GEMM_SMEM);
    cudaFuncSetAttribute((const void*)k_gemm<2,false>, cudaFuncAttributeMaxDynamicSharedMemorySize, GEMM_SMEM);

    // 1) W = Wq Wk^T, u = Wk bq
    k_precomp<<<DD + 1, DD>>>(Wq, Wk, bq);
    // 2) all splits/transposes + c
    k_prep<<<6656, 256>>>(inp, Wo);
    // 3) A' = X @ W -> fp16 splits
    k_gemm<1,false><<<dim3(ROWS/128, 2, 1), 256, GEMM_SMEM>>>(
        pXh, pXl, pWth, pWtl, nullptr, pAph, pApl, nullptr, nullptr,
        DD, DD, ROWS, 0, 0, 0);
    // 4) S = A' @ X^T  (per batch 2048x2048, K=256) -> fp32   [ncu-profiled slot]
    k_gemm<0,false><<<dim3(NN/128, NN/128, BB), 256, GEMM_SMEM>>>(
        pAph, pApl, pXh, pXl, pS, nullptr, nullptr, nullptr, nullptr,
        DD, NN, NN, (size_t)NN*DD, (size_t)NN*DD, (size_t)NN*NN);
    // 5) softmax -> Ph + 1/l
    k_softmax<<<ROWS/8, 256>>>();
    // 6) agg = (Ph @ X) / l  (K=2048, A hi-only: 2 combos) -> fp16 splits
    k_gemm<1,true><<<dim3(NN/128, 2, BB), 256, GEMM_SMEM>>>(
        pPh, nullptr, pXth, pXtl, nullptr, pAggh, pAggl, nullptr, pInvl,
        NN, DD, NN, (size_t)NN*NN, (size_t)DD*NN, (size_t)NN*DD);
    // 7) out = relu(agg @ Wo + bo) -> fp32
    k_gemm<2,false><<<dim3(ROWS/128, 2, 1), 256, GEMM_SMEM>>>(
        pAggh, pAggl, pWoth, pWotl, out, nullptr, nullptr, bo, nullptr,
        DD, DD, ROWS, 0, 0, 0);
}

// round 6
// speedup vs baseline: 1.0985x; 1.0985x over previous
#include <cuda_runtime.h>
#include <cuda_fp16.h>
#include <cstdint>

#define DD 256
#define BB 16
#define NN 2048
#define ROWS (BB*NN)

typedef __half h16;

// ------------------------------------------------------------------ scratch
__device__ float g_W[DD*DD];                 // Wq @ Wk^T
__device__ float g_u[DD];                    // Wk @ bq
__device__ float g_c[ROWS];                  // X . u  (per key row)
__device__ float g_invl[ROWS];               // 1 / sum(Ph)
__device__ float g_S[(size_t)ROWS*NN];       // scores (268MB)

__device__ h16 g_Xh[(size_t)ROWS*DD],  g_Xl[(size_t)ROWS*DD];    // X splits (row-major)
__device__ h16 g_Xth[(size_t)BB*DD*NN], g_Xtl[(size_t)BB*DD*NN]; // X^T splits
__device__ h16 g_Aph[(size_t)ROWS*DD], g_Apl[(size_t)ROWS*DD];   // A' = X@W splits
__device__ h16 g_Ph[(size_t)ROWS*NN];                            // softmax (hi only)
__device__ h16 g_aggh[(size_t)ROWS*DD], g_aggl[(size_t)ROWS*DD]; // agg splits
__device__ h16 g_Wth[DD*DD], g_Wtl[DD*DD];   // (WqWk^T)^T splits
__device__ h16 g_Woth[DD*DD], g_Wotl[DD*DD]; // Wo^T splits

// ------------------------------------------------------------------ helpers
__device__ __forceinline__ uint32_t smem_u32(const void* p) {
    uint32_t a;
    asm("{ .reg .u64 t; cvta.to.shared.u64 t, %1; cvt.u32.u64 %0, t; }" : "=r"(a) : "l"(p));
    return a;
}
#define CP16(dst, src) \
    asm volatile("cp.async.cg.shared.global [%0], [%1], 16;" :: "r"(dst), "l"(src))
#define CP_COMMIT() asm volatile("cp.async.commit_group;" ::: "memory")
#define CP_WAIT(n)  asm volatile("cp.async.wait_group %0;" :: "n"(n) : "memory")

#define MMA16816(c, a, b)                                                     \
    asm volatile("mma.sync.aligned.m16n8k16.row.col.f32.f16.f16.f32 "         \
        "{%0,%1,%2,%3},{%4,%5,%6,%7},{%8,%9},{%0,%1,%2,%3};"                  \
        : "+f"((c)[0]), "+f"((c)[1]), "+f"((c)[2]), "+f"((c)[3])              \
        : "r"((a)[0]), "r"((a)[1]), "r"((a)[2]), "r"((a)[3]),                 \
          "r"((b)[0]), "r"((b)[1]))

#define LDSM4(r0, r1, r2, r3, addr)                                           \
    asm volatile("ldmatrix.sync.aligned.m8n8.x4.shared.b16 {%0,%1,%2,%3}, [%4];" \
        : "=r"(r0), "=r"(r1), "=r"(r2), "=r"(r3) : "r"(addr))

__device__ __forceinline__ void split2(float f, h16& h, h16& l) {
    h = __float2half_rn(f);
    l = __float2half_rn(f - __half2float(h));
}

// ------------------------------------------------------------------ precompute: W = Wq@Wk^T, u = Wk@bq
__global__ void k_precomp(const float* __restrict__ Wq, const float* __restrict__ Wk,
                          const float* __restrict__ bq) {
    __shared__ float v[DD];
    int bx = blockIdx.x;
    if (bx < DD) {
        v[threadIdx.x] = Wq[bx*DD + threadIdx.x];
        __syncthreads();
        int j = threadIdx.x;
        const float* wk = Wk + j*DD;
        float s = 0.f;
#pragma unroll 8
        for (int e = 0; e < DD; e++) s += v[e] * wk[e];
        g_W[bx*DD + j] = s;
    } else {
        v[threadIdx.x] = bq[threadIdx.x];
        __syncthreads();
        int i = threadIdx.x;
        const float* wk = Wk + i*DD;
        float s = 0.f;
#pragma unroll 8
        for (int e = 0; e < DD; e++) s += wk[e] * v[e];
        g_u[i] = s;
    }
}

// ------------------------------------------------------------------ fused prep
__global__ __launch_bounds__(256) void k_prep(const float* __restrict__ X,
                                              const float* __restrict__ Wo) {
    __shared__ float t[64][65];
    __shared__ float us[DD];
    int bx = blockIdx.x, tid = threadIdx.x;
    if (bx < 512) {
        int which = bx >> 8, j = bx & 255, d = tid;
        const float* src = which ? Wo : g_W;
        h16* dh = which ? g_Woth : g_Wth;
        h16* dl = which ? g_Wotl : g_Wtl;
        float f = src[d*DD + j];
        split2(f, dh[j*DD + d], dl[j*DD + d]);
    } else if (bx < 4608) {
        if (tid < DD) us[tid] = g_u[tid];
        __syncthreads();
        int warp = (bx - 512)*8 + (tid >> 5);
        int lane = tid & 31;
        const float* x = X + (size_t)warp * DD;
        float c = 0.f;
#pragma unroll
        for (int i = 0; i < 8; i++) {
            int e = lane + 32*i;
            float f = x[e];
            c += f * us[e];
            split2(f, g_Xh[(size_t)warp*DD + e], g_Xl[(size_t)warp*DD + e]);
        }
#pragma unroll
        for (int o = 16; o; o >>= 1) c += __shfl_xor_sync(0xffffffffu, c, o);
        if (lane == 0) g_c[warp] = c;
    } else {
        int idx = bx - 4608;
        int n0 = (idx & 31) * 64, d0 = ((idx >> 5) & 3) * 64, b = idx >> 7;
        const float* Xb = X + (size_t)b * NN * DD;
        for (int u = tid; u < 64*16; u += 256) {
            int r = u >> 4, c4 = u & 15;
            float4 v = *(const float4*)(Xb + (size_t)(n0 + r)*DD + d0 + c4*4);
            t[r][c4*4+0] = v.x; t[r][c4*4+1] = v.y; t[r][c4*4+2] = v.z; t[r][c4*4+3] = v.w;
        }
        __syncthreads();
        size_t ob = (size_t)b * DD * NN;
        for (int u = tid; u < 4096; u += 256) {
            int r = u >> 6, c = u & 63;
            split2(t[c][r], g_Xth[ob + (size_t)(d0 + r)*NN + n0 + c],
                            g_Xtl[ob + (size_t)(d0 + r)*NN + n0 + c]);
        }
    }
}

// warp per row softmax: Ph = fp16(exp(S + c - max)), invl = 1/sum(Ph)
__global__ __launch_bounds__(256) void k_softmax() {
    int warp = (blockIdx.x * blockDim.x + threadIdx.x) >> 5;
    int lane = threadIdx.x & 31;
    int b = warp >> 11;
    const float* srow = g_S + (size_t)warp * NN;
    const float* crow = g_c + (size_t)b * NN;
    float v[64];
    float mx = -1e30f;
#pragma unroll
    for (int i = 0; i < 64; i++) {
        float s = srow[lane + 32*i] + crow[lane + 32*i];
        v[i] = s;
        mx = fmaxf(mx, s);
    }
#pragma unroll
    for (int o = 16; o; o >>= 1) mx = fmaxf(mx, __shfl_xor_sync(0xffffffffu, mx, o));
    float sum = 0.f;
    size_t ro = (size_t)warp * NN;
#pragma unroll
    for (int i = 0; i < 64; i++) {
        float p = __expf(v[i] - mx);
        h16 h = __float2half_rn(p);
        g_Ph[ro + lane + 32*i] = h;
        sum += __half2float(h);
    }
#pragma unroll
    for (int o = 16; o; o >>= 1) sum += __shfl_xor_sync(0xffffffffu, sum, o);
    if (lane == 0) g_invl[warp] = 1.f / sum;
}

// ------------------------------------------------------------------ HMMA GEMM
// C tile 128x128 = sum_k combos of fp16 splits.  SKIP_AL: A hi only (2 combos).
// R4 loop structure (2-stage, conditional commit), ldmatrix loads, 2 CTAs/SM.
#define TPAD   40                 // 32 data + 8 pad halfs per row -> 80B
#define TILE_B (128*TPAD*2)       // 10240
#define OFF_AH 0
#define OFF_AL (1*TILE_B)
#define OFF_BH (2*TILE_B)
#define OFF_BL (3*TILE_B)
#define STAGE_B (4*TILE_B)        // 40960
#define GEMM_SMEM (2*STAGE_B)     // 81920 -> two CTAs fit in 228KB

template<bool SKIP_AL>
__device__ __forceinline__ void issue_chunk(
    uint32_t sbase, const h16* __restrict__ pAh, const h16* __restrict__ pAl,
    const h16* __restrict__ pBh, const h16* __restrict__ pBl,
    int K, int k0, int tid)
{
#pragma unroll
    for (int i = 0; i < 2; i++) {
        int idx = tid + 256*i;
        int row = idx >> 2, seg = idx & 3;
        uint32_t doff = (uint32_t)(row*80 + seg*16);
        size_t goff = (size_t)row*K + k0 + seg*8;
        CP16(sbase + OFF_AH + doff, pAh + goff);
        if (!SKIP_AL) CP16(sbase + OFF_AL + doff, pAl + goff);
        CP16(sbase + OFF_BH + doff, pBh + goff);
        CP16(sbase + OFF_BL + doff, pBl + goff);
    }
}

// EPI: 0 = fp32   1 = fp16 hi/lo split with optional 1/l row scale   2 = bias+relu fp32
template<int EPI, bool SKIP_AL>
__global__ __launch_bounds__(256, 2) void k_gemm(
    const h16* __restrict__ Ah, const h16* __restrict__ Al,
    const h16* __restrict__ Bh, const h16* __restrict__ Bl,
    float* __restrict__ Cf, h16* __restrict__ Ch, h16* __restrict__ Cl,
    const float* __restrict__ bias, const float* __restrict__ invl,
    int K, int ldc, int Mrows, size_t sA, size_t sB, size_t sC)
{
    extern __shared__ char smem[];
    uint32_t sb = smem_u32(smem);
    int tid = threadIdx.x;
    int lane = tid & 31, wid = tid >> 5;
    int g = lane >> 2, t = lane & 3;
    int warp_m = (wid & 1) * 64;
    int warp_n = (wid >> 1) * 32;
    int m0 = blockIdx.x * 128, n0 = blockIdx.y * 128, b = blockIdx.z;

    // per-lane ldmatrix byte offsets within a tile (x4: 4 8x8 pieces)
    int lr = ((lane >> 3) & 1) * 8 + (lane & 7);
    int lk = (lane >> 4) * 16;
    uint32_t a_off[4], b_off[2];
#pragma unroll
    for (int i = 0; i < 4; i++) a_off[i] = (uint32_t)((warp_m + i*16 + lr)*80 + lk);
#pragma unroll
    for (int p = 0; p < 2; p++) b_off[p] = (uint32_t)((warp_n + p*16 + lr)*80 + lk);

    const h16* pAh = Ah + (size_t)b*sA + (size_t)m0*K;
    const h16* pAl = SKIP_AL ? nullptr : Al + (size_t)b*sA + (size_t)m0*K;
    const h16* pBh = Bh + (size_t)b*sB + (size_t)n0*K;
    const h16* pBl = Bl + (size_t)b*sB + (size_t)n0*K;

    float acc[4][4][4];
#pragma unroll
    for (int i = 0; i < 4; i++)
#pragma unroll
        for (int j = 0; j < 4; j++)
#pragma unroll
            for (int r = 0; r < 4; r++) acc[i][j][r] = 0.f;

    int nchunk = K >> 5;
    issue_chunk<SKIP_AL>(sb, pAh, pAl, pBh, pBl, K, 0, tid);
    CP_COMMIT();

    for (int ch = 0; ch < nchunk; ch++) {
        int st = ch & 1;
        if (ch + 1 < nchunk) {
            issue_chunk<SKIP_AL>(sb + (uint32_t)(st ^ 1)*STAGE_B, pAh, pAl, pBh, pBl,
                                 K, (ch+1) << 5, tid);
            CP_COMMIT();
            CP_WAIT(1);
        } else {
            CP_WAIT(0);
        }
        __syncthreads();

        uint32_t base = sb + (uint32_t)st * STAGE_B;
#pragma unroll
        for (int ks = 0; ks < 2; ks++) {
            uint32_t kb = ks * 32;
            uint32_t ah[4][4], al[4][4], bh[4][2], bl[4][2];
#pragma unroll
            for (int i = 0; i < 4; i++) {
                LDSM4(ah[i][0], ah[i][1], ah[i][2], ah[i][3], base + OFF_AH + a_off[i] + kb);
                if (!SKIP_AL)
                    LDSM4(al[i][0], al[i][1], al[i][2], al[i][3], base + OFF_AL + a_off[i] + kb);
            }
#pragma unroll
            for (int p = 0; p < 2; p++) {
                LDSM4(bh[2*p][0], bh[2*p+1][0], bh[2*p][1], bh[2*p+1][1],
                      base + OFF_BH + b_off[p] + kb);
                LDSM4(bl[2*p][0], bl[2*p+1][0], bl[2*p][1], bl[2*p+1][1],
                      base + OFF_BL + b_off[p] + kb);
            }
#pragma unroll
            for (int i = 0; i < 4; i++)
#pragma unroll
                for (int j = 0; j < 4; j++) {
                    MMA16816(acc[i][j], ah[i], bh[j]);
                    MMA16816(acc[i][j], ah[i], bl[j]);
                    if (!SKIP_AL) MMA16816(acc[i][j], al[i], bh[j]);
                }
        }
        __syncthreads();
    }

    // ---- epilogue ----
#pragma unroll
    for (int i = 0; i < 4; i++) {
        int row0 = m0 + warp_m + i*16 + g;
        float sc0 = 1.f, sc1 = 1.f;
        if (EPI == 1 && invl) {
            sc0 = invl[(size_t)b*Mrows + row0];
            sc1 = invl[(size_t)b*Mrows + row0 + 8];
        }
#pragma unroll
        for (int j = 0; j < 4; j++) {
            int col = n0 + warp_n + j*8 + 2*t;
            if (EPI == 0) {
                float* d0 = Cf + (size_t)b*sC + (size_t)row0*ldc + col;
                float* d1 = d0 + 8*ldc;
                *(float2*)d0 = make_float2(acc[i][j][0], acc[i][j][1]);
                *(float2*)d1 = make_float2(acc[i][j][2], acc[i][j][3]);
            } else if (EPI == 1) {
                float v0 = acc[i][j][0]*sc0, v1 = acc[i][j][1]*sc0;
                float v2 = acc[i][j][2]*sc1, v3 = acc[i][j][3]*sc1;
                h16 h0, l0, h1, l1, h2, l2, h3, l3;
                split2(v0, h0, l0); split2(v1, h1, l1);
                split2(v2, h2, l2); split2(v3, h3, l3);
                size_t o0 = (size_t)b*sC + (size_t)row0*ldc + col;
                size_t o1 = o0 + 8*(size_t)ldc;
                *(__half2*)(Ch + o0) = __halves2half2(h0, h1);
                *(__half2*)(Ch + o1) = __halves2half2(h2, h3);
                *(__half2*)(Cl + o0) = __halves2half2(l0, l1);
                *(__half2*)(Cl + o1) = __halves2half2(l2, l3);
            } else {
                float b0 = bias[col], b1 = bias[col+1];
                float* d0 = Cf + (size_t)row0*ldc + col;
                float* d1 = d0 + 8*ldc;
                *(float2*)d0 = make_float2(fmaxf(acc[i][j][0]+b0, 0.f),
                                           fmaxf(acc[i][j][1]+b1, 0.f));
                *(float2*)d1 = make_float2(fmaxf(acc[i][j][2]+b0, 0.f),
                                           fmaxf(acc[i][j][3]+b1, 0.f));
            }
        }
    }
}

// ------------------------------------------------------------------ launch
extern "C" void kernel_launch(void* const* d_in, const int* in_sizes, int n_in,
                              void* d_out, int out_size) {
    const float* inp = (const float*)d_in[0];
    const float* Wq  = (const float*)d_in[1];
    const float* bq  = (const float*)d_in[2];
    const float* Wk  = (const float*)d_in[3];
    // bk (d_in[4]) provably drops out of the softmax — unused.
    const float* Wo  = (const float*)d_in[5];
    const float* bo  = (const float*)d_in[6];
    float* out = (float*)d_out;

    float *pS, *pInvl;
    h16 *pXh, *pXl, *pXth, *pXtl, *pAph, *pApl, *pPh, *pAggh, *pAggl;
    h16 *pWth, *pWtl, *pWoth, *pWotl;
    cudaGetSymbolAddress((void**)&pS, g_S);
    cudaGetSymbolAddress((void**)&pInvl, g_invl);
    cudaGetSymbolAddress((void**)&pXh, g_Xh);   cudaGetSymbolAddress((void**)&pXl, g_Xl);
    cudaGetSymbolAddress((void**)&pXth, g_Xth); cudaGetSymbolAddress((void**)&pXtl, g_Xtl);
    cudaGetSymbolAddress((void**)&pAph, g_Aph); cudaGetSymbolAddress((void**)&pApl, g_Apl);
    cudaGetSymbolAddress((void**)&pPh, g_Ph);
    cudaGetSymbolAddress((void**)&pAggh, g_aggh); cudaGetSymbolAddress((void**)&pAggl, g_aggl);
    cudaGetSymbolAddress((void**)&pWth, g_Wth); cudaGetSymbolAddress((void**)&pWtl, g_Wtl);
    cudaGetSymbolAddress((void**)&pWoth, g_Woth); cudaGetSymbolAddress((void**)&pWotl, g_Wotl);

    cudaFuncSetAttribute((const void*)k_gemm<0,false>, cudaFuncAttributeMaxDynamicSharedMemorySize, GEMM_SMEM);
    cudaFuncSetAttribute((const void*)k_gemm<1,false>, cudaFuncAttributeMaxDynamicSharedMemorySize, GEMM_SMEM);
    cudaFuncSetAttribute((const void*)k_gemm<1,true>,  cudaFuncAttributeMaxDynamicSharedMemorySize, GEMM_SMEM);
    cudaFuncSetAttribute((const void*)k_gemm<2,false>, cudaFuncAttributeMaxDynamicSharedMemorySize, GEMM_SMEM);

    // 1) W = Wq Wk^T, u = Wk bq
    k_precomp<<<DD + 1, DD>>>(Wq, Wk, bq);
    // 2) all splits/transposes + c
    k_prep<<<6656, 256>>>(inp, Wo);
    // 3) A' = X @ W -> fp16 splits
    k_gemm<1,false><<<dim3(ROWS/128, 2, 1), 256, GEMM_SMEM>>>(
        pXh, pXl, pWth, pWtl, nullptr, pAph, pApl, nullptr, nullptr,
        DD, DD, ROWS, 0, 0, 0);
    // 4) S = A' @ X^T  (per batch 2048x2048, K=256) -> fp32   [ncu-profiled slot]
    k_gemm<0,false><<<dim3(NN/128, NN/128, BB), 256, GEMM_SMEM>>>(
        pAph, pApl, pXh, pXl, pS, nullptr, nullptr, nullptr, nullptr,
        DD, NN, NN, (size_t)NN*DD, (size_t)NN*DD, (size_t)NN*NN);
    // 5) softmax -> Ph + 1/l
    k_softmax<<<ROWS/8, 256>>>();
    // 6) agg = (Ph @ X) / l  (K=2048, A hi-only: 2 combos) -> fp16 splits
    k_gemm<1,true><<<dim3(NN/128, 2, BB), 256, GEMM_SMEM>>>(
        pPh, nullptr, pXth, pXtl, nullptr, pAggh, pAggl, nullptr, pInvl,
        NN, DD, NN, (size_t)NN*NN, (size_t)DD*NN, (size_t)NN*DD);
    // 7) out = relu(agg @ Wo + bo) -> fp32
    k_gemm<2,false><<<dim3(ROWS/128, 2, 1), 256, GEMM_SMEM>>>(
        pAggh, pAggl, pWoth, pWotl, out, nullptr, nullptr, bo, nullptr,
        DD, DD, ROWS, 0, 0, 0);
}

// round 7
// speedup vs baseline: 1.2574x; 1.1446x over previous
#include <cuda_runtime.h>
#include <cuda_fp16.h>
#include <cstdint>

#define DD 256
#define BB 16
#define NN 2048
#define ROWS (BB*NN)

typedef __half h16;

// ------------------------------------------------------------------ scratch
__device__ float g_W[DD*DD];                 // Wq @ Wk^T
__device__ float g_u[DD];                    // Wk @ bq
__device__ float g_c[ROWS];                  // X . u  (per key row)
__device__ float g_invl[ROWS];               // 1 / sum(Ph)
__device__ float g_S[(size_t)ROWS*NN];       // scores (268MB)

__device__ h16 g_Xh[(size_t)ROWS*DD],  g_Xl[(size_t)ROWS*DD];    // X splits (row-major)
__device__ h16 g_Xth[(size_t)BB*DD*NN];                          // X^T (hi only)
__device__ h16 g_Aph[(size_t)ROWS*DD], g_Apl[(size_t)ROWS*DD];   // A' = X@W splits
__device__ h16 g_Ph[(size_t)ROWS*NN];                            // softmax (hi only)
__device__ h16 g_aggh[(size_t)ROWS*DD], g_aggl[(size_t)ROWS*DD]; // agg splits
__device__ h16 g_Wth[DD*DD], g_Wtl[DD*DD];   // (WqWk^T)^T splits
__device__ h16 g_Woth[DD*DD], g_Wotl[DD*DD]; // Wo^T splits

// ------------------------------------------------------------------ helpers
__device__ __forceinline__ uint32_t smem_u32(const void* p) {
    uint32_t a;
    asm("{ .reg .u64 t; cvta.to.shared.u64 t, %1; cvt.u32.u64 %0, t; }" : "=r"(a) : "l"(p));
    return a;
}
#define CP16(dst, src) \
    asm volatile("cp.async.cg.shared.global [%0], [%1], 16;" :: "r"(dst), "l"(src))
#define CP_COMMIT() asm volatile("cp.async.commit_group;" ::: "memory")
#define CP_WAIT(n)  asm volatile("cp.async.wait_group %0;" :: "n"(n) : "memory")

#define MMA16816(c, a, b)                                                     \
    asm volatile("mma.sync.aligned.m16n8k16.row.col.f32.f16.f16.f32 "         \
        "{%0,%1,%2,%3},{%4,%5,%6,%7},{%8,%9},{%0,%1,%2,%3};"                  \
        : "+f"((c)[0]), "+f"((c)[1]), "+f"((c)[2]), "+f"((c)[3])              \
        : "r"((a)[0]), "r"((a)[1]), "r"((a)[2]), "r"((a)[3]),                 \
          "r"((b)[0]), "r"((b)[1]))

#define LDSM4(r0, r1, r2, r3, addr)                                           \
    asm volatile("ldmatrix.sync.aligned.m8n8.x4.shared.b16 {%0,%1,%2,%3}, [%4];" \
        : "=r"(r0), "=r"(r1), "=r"(r2), "=r"(r3) : "r"(addr))

__device__ __forceinline__ void split2(float f, h16& h, h16& l) {
    h = __float2half_rn(f);
    l = __float2half_rn(f - __half2float(h));
}

// ------------------------------------------------------------------ precompute: W = Wq@Wk^T, u = Wk@bq
__global__ void k_precomp(const float* __restrict__ Wq, const float* __restrict__ Wk,
                          const float* __restrict__ bq) {
    __shared__ float v[DD];
    int bx = blockIdx.x;
    if (bx < DD) {
        v[threadIdx.x] = Wq[bx*DD + threadIdx.x];
        __syncthreads();
        int j = threadIdx.x;
        const float* wk = Wk + j*DD;
        float s = 0.f;
#pragma unroll 8
        for (int e = 0; e < DD; e++) s += v[e] * wk[e];
        g_W[bx*DD + j] = s;
    } else {
        v[threadIdx.x] = bq[threadIdx.x];
        __syncthreads();
        int i = threadIdx.x;
        const float* wk = Wk + i*DD;
        float s = 0.f;
#pragma unroll 8
        for (int e = 0; e < DD; e++) s += wk[e] * v[e];
        g_u[i] = s;
    }
}

// ------------------------------------------------------------------ fused prep
__global__ __launch_bounds__(256) void k_prep(const float* __restrict__ X,
                                              const float* __restrict__ Wo) {
    __shared__ float t[64][65];
    __shared__ float us[DD];
    int bx = blockIdx.x, tid = threadIdx.x;
    if (bx < 512) {
        int which = bx >> 8, j = bx & 255, d = tid;
        const float* src = which ? Wo : g_W;
        h16* dh = which ? g_Woth : g_Wth;
        h16* dl = which ? g_Wotl : g_Wtl;
        float f = src[d*DD + j];
        split2(f, dh[j*DD + d], dl[j*DD + d]);
    } else if (bx < 4608) {
        if (tid < DD) us[tid] = g_u[tid];
        __syncthreads();
        int warp = (bx - 512)*8 + (tid >> 5);
        int lane = tid & 31;
        const float* x = X + (size_t)warp * DD;
        float c = 0.f;
#pragma unroll
        for (int i = 0; i < 8; i++) {
            int e = lane + 32*i;
            float f = x[e];
            c += f * us[e];
            split2(f, g_Xh[(size_t)warp*DD + e], g_Xl[(size_t)warp*DD + e]);
        }
#pragma unroll
        for (int o = 16; o; o >>= 1) c += __shfl_xor_sync(0xffffffffu, c, o);
        if (lane == 0) g_c[warp] = c;
    } else {
        int idx = bx - 4608;
        int n0 = (idx & 31) * 64, d0 = ((idx >> 5) & 3) * 64, b = idx >> 7;
        const float* Xb = X + (size_t)b * NN * DD;
        for (int u = tid; u < 64*16; u += 256) {
            int r = u >> 4, c4 = u & 15;
            float4 v = *(const float4*)(Xb + (size_t)(n0 + r)*DD + d0 + c4*4);
            t[r][c4*4+0] = v.x; t[r][c4*4+1] = v.y; t[r][c4*4+2] = v.z; t[r][c4*4+3] = v.w;
        }
        __syncthreads();
        size_t ob = (size_t)b * DD * NN;
        for (int u = tid; u < 4096; u += 256) {
            int r = u >> 6, c = u & 63;
            g_Xth[ob + (size_t)(d0 + r)*NN + n0 + c] = __float2half_rn(t[c][r]);
        }
    }
}

// warp per row softmax: Ph = fp16(exp(S + c - max)), invl = 1/sum(Ph)
__global__ __launch_bounds__(256) void k_softmax() {
    int warp = (blockIdx.x * blockDim.x + threadIdx.x) >> 5;
    int lane = threadIdx.x & 31;
    int b = warp >> 11;
    const float* srow = g_S + (size_t)warp * NN;
    const float* crow = g_c + (size_t)b * NN;
    float v[64];
    float mx = -1e30f;
#pragma unroll
    for (int i = 0; i < 64; i++) {
        float s = srow[lane + 32*i] + crow[lane + 32*i];
        v[i] = s;
        mx = fmaxf(mx, s);
    }
#pragma unroll
    for (int o = 16; o; o >>= 1) mx = fmaxf(mx, __shfl_xor_sync(0xffffffffu, mx, o));
    float sum = 0.f;
    size_t ro = (size_t)warp * NN;
#pragma unroll
    for (int i = 0; i < 64; i++) {
        float p = __expf(v[i] - mx);
        h16 h = __float2half_rn(p);
        g_Ph[ro + lane + 32*i] = h;
        sum += __half2float(h);
    }
#pragma unroll
    for (int o = 16; o; o >>= 1) sum += __shfl_xor_sync(0xffffffffu, sum, o);
    if (lane == 0) g_invl[warp] = 1.f / sum;
}

// ------------------------------------------------------------------ HMMA GEMM
// COMBOS: 3 = Ah.Bh + Ah.Bl + Al.Bh   2 = Ah.Bh + Ah.Bl   1 = Ah.Bh
#define TPAD   40                 // 32 data + 8 pad halfs per row -> 80B
#define TILE_B (128*TPAD*2)       // 10240
#define OFF_AH 0
#define OFF_AL (1*TILE_B)
#define OFF_BH (2*TILE_B)
#define OFF_BL (3*TILE_B)
#define STAGE_B (4*TILE_B)        // 40960
#define GEMM_SMEM (2*STAGE_B)     // 81920 -> two CTAs per SM

// EPI: 0 = fp32   1 = fp16 hi/lo split with optional 1/l row scale   2 = bias+relu fp32
template<int EPI, int COMBOS>
__global__ __launch_bounds__(256, 2) void k_gemm(
    const h16* __restrict__ Ah, const h16* __restrict__ Al,
    const h16* __restrict__ Bh, const h16* __restrict__ Bl,
    float* __restrict__ Cf, h16* __restrict__ Ch, h16* __restrict__ Cl,
    const float* __restrict__ bias, const float* __restrict__ invl,
    int K, int ldc, int Mrows, size_t sA, size_t sB, size_t sC)
{
    extern __shared__ char smem[];
    uint32_t sb = smem_u32(smem);
    int tid = threadIdx.x;
    int lane = tid & 31, wid = tid >> 5;
    int g = lane >> 2, t = lane & 3;
    int warp_m = (wid & 1) * 64;
    int warp_n = (wid >> 1) * 32;
    int m0 = blockIdx.x * 128, n0 = blockIdx.y * 128, b = blockIdx.z;

    // hoisted per-thread cp.async offsets (row = tid>>2, seg = tid&3; +256 -> row+64)
    size_t go0 = (size_t)(tid >> 2) * K + (tid & 3) * 8;
    size_t go1 = go0 + (size_t)64 * K;
    uint32_t do0 = (uint32_t)((tid >> 2) * 80 + (tid & 3) * 16);
    uint32_t do1 = do0 + 64*80;

    // per-lane ldmatrix byte offsets within a tile
    int lr = ((lane >> 3) & 1) * 8 + (lane & 7);
    int lk = (lane >> 4) * 16;
    uint32_t a_off[4], b_off[2];
#pragma unroll
    for (int i = 0; i < 4; i++) a_off[i] = (uint32_t)((warp_m + i*16 + lr)*80 + lk);
#pragma unroll
    for (int p = 0; p < 2; p++) b_off[p] = (uint32_t)((warp_n + p*16 + lr)*80 + lk);

    const h16* pAh = Ah + (size_t)b*sA + (size_t)m0*K;
    const h16* pAl = (COMBOS >= 3) ? Al + (size_t)b*sA + (size_t)m0*K : nullptr;
    const h16* pBh = Bh + (size_t)b*sB + (size_t)n0*K;
    const h16* pBl = (COMBOS >= 2) ? Bl + (size_t)b*sB + (size_t)n0*K : nullptr;

    float acc[4][4][4];
#pragma unroll
    for (int i = 0; i < 4; i++)
#pragma unroll
        for (int j = 0; j < 4; j++)
#pragma unroll
            for (int r = 0; r < 4; r++) acc[i][j][r] = 0.f;

#define ISSUE_CHUNK(sbase, k0) do {                                          \
        CP16((sbase) + OFF_AH + do0, pAh + go0 + (k0));                      \
        CP16((sbase) + OFF_AH + do1, pAh + go1 + (k0));                      \
        if (COMBOS >= 3) {                                                   \
            CP16((sbase) + OFF_AL + do0, pAl + go0 + (k0));                  \
            CP16((sbase) + OFF_AL + do1, pAl + go1 + (k0));                  \
        }                                                                    \
        CP16((sbase) + OFF_BH + do0, pBh + go0 + (k0));                      \
        CP16((sbase) + OFF_BH + do1, pBh + go1 + (k0));                      \
        if (COMBOS >= 2) {                                                   \
            CP16((sbase) + OFF_BL + do0, pBl + go0 + (k0));                  \
            CP16((sbase) + OFF_BL + do1, pBl + go1 + (k0));                  \
        }                                                                    \
    } while (0)

    int nchunk = K >> 5;
    ISSUE_CHUNK(sb, 0);
    CP_COMMIT();

    for (int ch = 0; ch < nchunk; ch++) {
        int st = ch & 1;
        if (ch + 1 < nchunk) {
            ISSUE_CHUNK(sb + (uint32_t)(st ^ 1)*STAGE_B, (ch+1) << 5);
            CP_COMMIT();
            CP_WAIT(1);
        } else {
            CP_WAIT(0);
        }
        __syncthreads();

        uint32_t base = sb + (uint32_t)st * STAGE_B;
#pragma unroll
        for (int ks = 0; ks < 2; ks++) {
            uint32_t kb = ks * 32;
            uint32_t ah[4][4], al[4][4], bh[4][2], bl[4][2];
#pragma unroll
            for (int i = 0; i < 4; i++) {
                LDSM4(ah[i][0], ah[i][1], ah[i][2], ah[i][3], base + OFF_AH + a_off[i] + kb);
                if (COMBOS >= 3)
                    LDSM4(al[i][0], al[i][1], al[i][2], al[i][3], base + OFF_AL + a_off[i] + kb);
            }
#pragma unroll
            for (int p = 0; p < 2; p++) {
                LDSM4(bh[2*p][0], bh[2*p+1][0], bh[2*p][1], bh[2*p+1][1],
                      base + OFF_BH + b_off[p] + kb);
                if (COMBOS >= 2)
                    LDSM4(bl[2*p][0], bl[2*p+1][0], bl[2*p][1], bl[2*p+1][1],
                          base + OFF_BL + b_off[p] + kb);
            }
#pragma unroll
            for (int i = 0; i < 4; i++)
#pragma unroll
                for (int j = 0; j < 4; j++) {
                    MMA16816(acc[i][j], ah[i], bh[j]);
                    if (COMBOS >= 2) MMA16816(acc[i][j], ah[i], bl[j]);
                    if (COMBOS >= 3) MMA16816(acc[i][j], al[i], bh[j]);
                }
        }
        __syncthreads();
    }

    // ---- epilogue ----
#pragma unroll
    for (int i = 0; i < 4; i++) {
        int row0 = m0 + warp_m + i*16 + g;
        float sc0 = 1.f, sc1 = 1.f;
        if (EPI == 1 && invl) {
            sc0 = invl[(size_t)b*Mrows + row0];
            sc1 = invl[(size_t)b*Mrows + row0 + 8];
        }
#pragma unroll
        for (int j = 0; j < 4; j++) {
            int col = n0 + warp_n + j*8 + 2*t;
            if (EPI == 0) {
                float* d0 = Cf + (size_t)b*sC + (size_t)row0*ldc + col;
                float* d1 = d0 + 8*ldc;
                *(float2*)d0 = make_float2(acc[i][j][0], acc[i][j][1]);
                *(float2*)d1 = make_float2(acc[i][j][2], acc[i][j][3]);
            } else if (EPI == 1) {
                float v0 = acc[i][j][0]*sc0, v1 = acc[i][j][1]*sc0;
                float v2 = acc[i][j][2]*sc1, v3 = acc[i][j][3]*sc1;
                h16 h0, l0, h1, l1, h2, l2, h3, l3;
                split2(v0, h0, l0); split2(v1, h1, l1);
                split2(v2, h2, l2); split2(v3, h3, l3);
                size_t o0 = (size_t)b*sC + (size_t)row0*ldc + col;
                size_t o1 = o0 + 8*(size_t)ldc;
                *(__half2*)(Ch + o0) = __halves2half2(h0, h1);
                *(__half2*)(Ch + o1) = __halves2half2(h2, h3);
                *(__half2*)(Cl + o0) = __halves2half2(l0, l1);
                *(__half2*)(Cl + o1) = __halves2half2(l2, l3);
            } else {
                float b0 = bias[col], b1 = bias[col+1];
                float* d0 = Cf + (size_t)row0*ldc + col;
                float* d1 = d0 + 8*ldc;
                *(float2*)d0 = make_float2(fmaxf(acc[i][j][0]+b0, 0.f),
                                           fmaxf(acc[i][j][1]+b1, 0.f));
                *(float2*)d1 = make_float2(fmaxf(acc[i][j][2]+b0, 0.f),
                                           fmaxf(acc[i][j][3]+b1, 0.f));
            }
        }
    }
#undef ISSUE_CHUNK
}

// ------------------------------------------------------------------ launch
extern "C" void kernel_launch(void* const* d_in, const int* in_sizes, int n_in,
                              void* d_out, int out_size) {
    const float* inp = (const float*)d_in[0];
    const float* Wq  = (const float*)d_in[1];
    const float* bq  = (const float*)d_in[2];
    const float* Wk  = (const float*)d_in[3];
    // bk (d_in[4]) provably drops out of the softmax — unused.
    const float* Wo  = (const float*)d_in[5];
    const float* bo  = (const float*)d_in[6];
    float* out = (float*)d_out;

    float *pS, *pInvl;
    h16 *pXh, *pXl, *pXth, *pAph, *pApl, *pPh, *pAggh, *pAggl;
    h16 *pWth, *pWtl, *pWoth, *pWotl;
    cudaGetSymbolAddress((void**)&pS, g_S);
    cudaGetSymbolAddress((void**)&pInvl, g_invl);
    cudaGetSymbolAddress((void**)&pXh, g_Xh);   cudaGetSymbolAddress((void**)&pXl, g_Xl);
    cudaGetSymbolAddress((void**)&pXth, g_Xth);
    cudaGetSymbolAddress((void**)&pAph, g_Aph); cudaGetSymbolAddress((void**)&pApl, g_Apl);
    cudaGetSymbolAddress((void**)&pPh, g_Ph);
    cudaGetSymbolAddress((void**)&pAggh, g_aggh); cudaGetSymbolAddress((void**)&pAggl, g_aggl);
    cudaGetSymbolAddress((void**)&pWth, g_Wth); cudaGetSymbolAddress((void**)&pWtl, g_Wtl);
    cudaGetSymbolAddress((void**)&pWoth, g_Woth); cudaGetSymbolAddress((void**)&pWotl, g_Wotl);

    cudaFuncSetAttribute((const void*)k_gemm<0,3>, cudaFuncAttributeMaxDynamicSharedMemorySize, GEMM_SMEM);
    cudaFuncSetAttribute((const void*)k_gemm<1,3>, cudaFuncAttributeMaxDynamicSharedMemorySize, GEMM_SMEM);
    cudaFuncSetAttribute((const void*)k_gemm<1,1>, cudaFuncAttributeMaxDynamicSharedMemorySize, GEMM_SMEM);
    cudaFuncSetAttribute((const void*)k_gemm<2,3>, cudaFuncAttributeMaxDynamicSharedMemorySize, GEMM_SMEM);

    // 1) W = Wq Wk^T, u = Wk bq
    k_precomp<<<DD + 1, DD>>>(Wq, Wk, bq);
    // 2) all splits/transposes + c
    k_prep<<<6656, 256>>>(inp, Wo);
    // 3) A' = X @ W -> fp16 splits  (3 combos)
    k_gemm<1,3><<<dim3(ROWS/128, 2, 1), 256, GEMM_SMEM>>>(
        pXh, pXl, pWth, pWtl, nullptr, pAph, pApl, nullptr, nullptr,
        DD, DD, ROWS, 0, 0, 0);
    // 4) S = A' @ X^T  (per batch 2048x2048, K=256) -> fp32  (3 combos) [profiled]
    k_gemm<0,3><<<dim3(NN/128, NN/128, BB), 256, GEMM_SMEM>>>(
        pAph, pApl, pXh, pXl, pS, nullptr, nullptr, nullptr, nullptr,
        DD, NN, NN, (size_t)NN*DD, (size_t)NN*DD, (size_t)NN*NN);
    // 5) softmax -> Ph + 1/l
    k_softmax<<<ROWS/8, 256>>>();
    // 6) agg = (Ph @ Xth) / l  (K=2048, SINGLE combo) -> fp16 splits
    k_gemm<1,1><<<dim3(NN/128, 2, BB), 256, GEMM_SMEM>>>(
        pPh, nullptr, pXth, nullptr, nullptr, pAggh, pAggl, nullptr, pInvl,
        NN, DD, NN, (size_t)NN*NN, (size_t)DD*NN, (size_t)NN*DD);
    // 7) out = relu(agg @ Wo + bo) -> fp32  (3 combos)
    k_gemm<2,3><<<dim3(ROWS/128, 2, 1), 256, GEMM_SMEM>>>(
        pAggh, pAggl, pWoth, pWotl, out, nullptr, nullptr, bo, nullptr,
        DD, DD, ROWS, 0, 0, 0);
}